// round 11
// baseline (speedup 1.0000x reference)
#include <cuda_runtime.h>
#include <cuda_fp16.h>
#include <mma.h>
#include <cstdint>

using namespace nvcuda;

// Problem constants (fixed by setup_inputs)
#define T_TOK   8192
#define IN_F    2048
#define OUT_F   2048
#define N_EXP   8
#define GATE_N  128
#define Z_N     256
#define K2P     320               // 256 z + 8 w_dense + 1 const-one + 55 pad
#define KTOT    (IN_F + K2P)      // 2368

// ---------------------------------------------------------------------------
// Static device scratch (no allocation allowed)
// ---------------------------------------------------------------------------
__device__ __half g_xh[(size_t)T_TOK * IN_F];
__device__ __half g_xl[(size_t)T_TOK * IN_F];
__device__ __half g_Wh[(size_t)OUT_F * IN_F];
__device__ __half g_gwh[GATE_N * IN_F];
__device__ __half g_gwl[GATE_N * IN_F];
__device__ __half g_svh[Z_N * IN_F];
__device__ float  g_g[(size_t)T_TOK * GATE_N];
__device__ float  g_z[(size_t)T_TOK * Z_N];
__device__ __half g_zc[(size_t)T_TOK * K2P];
__device__ __half g_u2[(size_t)OUT_F * K2P];

// ---------------------------------------------------------------------------
__device__ __forceinline__ uint32_t smem_u32(const void* p) {
    uint32_t a;
    asm("{ .reg .u64 t; cvta.to.shared.u64 t, %1; cvt.u32.u64 %0, t; }"
        : "=r"(a) : "l"(p));
    return a;
}
__device__ __forceinline__ void cp16(uint32_t saddr, const void* gaddr) {
    asm volatile("cp.async.cg.shared.global [%0], [%1], 16;" :: "r"(saddr), "l"(gaddr));
}
__device__ __forceinline__ void cp_commit() {
    asm volatile("cp.async.commit_group;" ::: "memory");
}
template<int N>
__device__ __forceinline__ void cp_wait() {
    asm volatile("cp.async.wait_group %0;" :: "n"(N) : "memory");
}

#define SKT 40   // smem row stride in halves (32 data + 8 pad) = 80 bytes

// ---------------------------------------------------------------------------
// fp16 wmma GEMM, C[M,N] = A[M,K]@B[N,K]^T, fp32 store.
// Dual-segment K: cols [0,K0) from A0/B0, cols [K0,Ktot) from A1/B1.
// BM=128, BN template (256 or 128), BK=32, 256 threads.
// 8 warps as 2(row) x 4(col); warp tile 64 x (BN/4). 3-stage cp.async.
// ---------------------------------------------------------------------------
template<int BN>
__global__ __launch_bounds__(256) void gemm_f16_big(
    const __half* __restrict__ A0, int lda0, const __half* __restrict__ A1, int lda1,
    const __half* __restrict__ B0, int ldb0, const __half* __restrict__ B1, int ldb1,
    float* __restrict__ C, int ldc, int K0, int Ktot)
{
    extern __shared__ __half sm[];
    constexpr int ATL = 128 * SKT;                 // halves
    constexpr int BTL = BN * SKT;
    constexpr int STG = ATL + BTL;                 // per stage (halves)
    constexpr int WN  = BN / 4;                    // warp N extent
    constexpr int NF  = WN / 16;                   // B frags per warp
    const uint32_t sbase = smem_u32(sm);

    const int tid  = threadIdx.x;
    const int wid  = tid >> 5;
    const int wrow = wid & 1;                      // 0..1 -> 64-row band
    const int wcol = wid >> 1;                     // 0..3 -> WN-col band
    const int m0 = blockIdx.y * 128;
    const int n0 = blockIdx.x * BN;

    wmma::fragment<wmma::accumulator, 16, 16, 16, float> c[4][NF];
#pragma unroll
    for (int i = 0; i < 4; i++)
#pragma unroll
        for (int j = 0; j < NF; j++)
            wmma::fill_fragment(c[i][j], 0.0f);

    const int nt = Ktot / 32;

    auto load_tile = [&](int kt) {
        const int s = kt % 3;
        const int k0 = kt * 32;
        const __half* Asrc; int lda; int ka;
        const __half* Bsrc; int ldb;
        if (k0 < K0) { Asrc = A0; lda = lda0; Bsrc = B0; ldb = ldb0; ka = k0; }
        else         { Asrc = A1; lda = lda1; Bsrc = B1; ldb = ldb1; ka = k0 - K0; }
        const uint32_t st = sbase + s * STG * 2;
        // (128+BN) rows x 4 chunks of 16B
#pragma unroll
        for (int cch = 0; cch < (128 + BN) * 4; cch += 256) {
            int idx = cch + tid;
            int r = idx >> 2, q = idx & 3;
            if (r < 128)
                cp16(st + r * 80 + q * 16, Asrc + (size_t)(m0 + r) * lda + ka + q * 8);
            else
                cp16(st + ATL * 2 + (r - 128) * 80 + q * 16,
                     Bsrc + (size_t)(n0 + r - 128) * ldb + ka + q * 8);
        }
        cp_commit();
    };

    auto compute = [&](int kt) {
        const int s = kt % 3;
        __half* Asm = sm + s * STG;
        __half* Bsm = sm + s * STG + ATL;
#pragma unroll
        for (int kk = 0; kk < 32; kk += 16) {
            wmma::fragment<wmma::matrix_a, 16, 16, 16, __half, wmma::row_major> a[4];
            wmma::fragment<wmma::matrix_b, 16, 16, 16, __half, wmma::col_major> bf[NF];
#pragma unroll
            for (int i = 0; i < 4; i++)
                wmma::load_matrix_sync(a[i], &Asm[(wrow * 64 + i * 16) * SKT + kk], SKT);
#pragma unroll
            for (int j = 0; j < NF; j++)
                wmma::load_matrix_sync(bf[j], &Bsm[(wcol * WN + j * 16) * SKT + kk], SKT);
#pragma unroll
            for (int i = 0; i < 4; i++)
#pragma unroll
                for (int j = 0; j < NF; j++)
                    wmma::mma_sync(c[i][j], a[i], bf[j], c[i][j]);
        }
    };

    load_tile(0);
    if (nt > 1) load_tile(1);
    for (int kt = 0; kt < nt; kt++) {
        if (kt + 2 < nt) { load_tile(kt + 2); cp_wait<2>(); }
        else if (kt + 1 < nt) cp_wait<1>();
        else cp_wait<0>();
        __syncthreads();
        compute(kt);
        __syncthreads();
    }

#pragma unroll
    for (int i = 0; i < 4; i++)
#pragma unroll
        for (int j = 0; j < NF; j++)
            wmma::store_matrix_sync(
                &C[(size_t)(m0 + wrow * 64 + i * 16) * ldc + n0 + wcol * WN + j * 16],
                c[i][j], ldc, wmma::mem_row_major);
}

// ---------------------------------------------------------------------------
// Split (hi/lo) fp16 GEMM for the gate: ~fp32 accuracy (3 MMAs per frag).
// BM=128, BN=64, BK=32, 256 threads (8 warps as 4x2, warp tile 32x32).
// ---------------------------------------------------------------------------
__global__ __launch_bounds__(256) void gemm_split_kernel(
    const __half* __restrict__ Ah, const __half* __restrict__ Al, int lda,
    const __half* __restrict__ Bh, const __half* __restrict__ Bl, int ldb,
    float* __restrict__ C, int ldc, int Ktot)
{
    extern __shared__ __half sm[];
    constexpr int ATL = 128 * SKT;
    constexpr int BTL = 64 * SKT;
    constexpr int STG = 2 * ATL + 2 * BTL;
    const uint32_t sbase = smem_u32(sm);

    const int tid = threadIdx.x;
    const int wid = tid >> 5;
    const int wrow = wid >> 1;
    const int wcol = wid & 1;
    const int m0 = blockIdx.y * 128;
    const int n0 = blockIdx.x * 64;

    wmma::fragment<wmma::accumulator, 16, 16, 16, float> c[2][2];
#pragma unroll
    for (int i = 0; i < 2; i++)
#pragma unroll
        for (int j = 0; j < 2; j++)
            wmma::fill_fragment(c[i][j], 0.0f);

    const int nt = Ktot / 32;

    auto load_tile = [&](int s, int kt) {
        const int k0 = kt * 32;
        const uint32_t st = sbase + s * STG * 2;
#pragma unroll
        for (int it = 0; it < 2; it++) {
            int cch = tid + it * 256;
            int r = cch >> 2, q = cch & 3;
            cp16(st + r * 80 + q * 16, Ah + (size_t)(m0 + r) * lda + k0 + q * 8);
            cp16(st + ATL * 2 + r * 80 + q * 16, Al + (size_t)(m0 + r) * lda + k0 + q * 8);
        }
        {
            int cch = tid;
            int r = cch >> 2, q = cch & 3;
            cp16(st + 4 * ATL + r * 80 + q * 16, Bh + (size_t)(n0 + r) * ldb + k0 + q * 8);
            cp16(st + 4 * ATL + 2 * BTL + r * 80 + q * 16,
                 Bl + (size_t)(n0 + r) * ldb + k0 + q * 8);
        }
        cp_commit();
    };

    auto compute = [&](int s) {
        __half* AhS = sm + s * STG;
        __half* AlS = AhS + ATL;
        __half* BhS = AlS + ATL;
        __half* BlS = BhS + BTL;
#pragma unroll
        for (int kk = 0; kk < 32; kk += 16) {
            wmma::fragment<wmma::matrix_a, 16, 16, 16, __half, wmma::row_major> ah[2], al[2];
            wmma::fragment<wmma::matrix_b, 16, 16, 16, __half, wmma::col_major> bh[2], bl[2];
#pragma unroll
            for (int i = 0; i < 2; i++) {
                wmma::load_matrix_sync(ah[i], &AhS[(wrow * 32 + i * 16) * SKT + kk], SKT);
                wmma::load_matrix_sync(al[i], &AlS[(wrow * 32 + i * 16) * SKT + kk], SKT);
            }
#pragma unroll
            for (int j = 0; j < 2; j++) {
                wmma::load_matrix_sync(bh[j], &BhS[(wcol * 32 + j * 16) * SKT + kk], SKT);
                wmma::load_matrix_sync(bl[j], &BlS[(wcol * 32 + j * 16) * SKT + kk], SKT);
            }
#pragma unroll
            for (int i = 0; i < 2; i++)
#pragma unroll
                for (int j = 0; j < 2; j++) {
                    wmma::mma_sync(c[i][j], ah[i], bl[j], c[i][j]);
                    wmma::mma_sync(c[i][j], al[i], bh[j], c[i][j]);
                    wmma::mma_sync(c[i][j], ah[i], bh[j], c[i][j]);
                }
        }
    };

    load_tile(0, 0);
    for (int kt = 0; kt < nt; kt++) {
        const int s = kt & 1;
        if (kt + 1 < nt) { load_tile(s ^ 1, kt + 1); cp_wait<1>(); }
        else             { cp_wait<0>(); }
        __syncthreads();
        compute(s);
        __syncthreads();
    }

#pragma unroll
    for (int i = 0; i < 2; i++)
#pragma unroll
        for (int j = 0; j < 2; j++)
            wmma::store_matrix_sync(
                &C[(size_t)(m0 + wrow * 32 + i * 16) * ldc + n0 + wcol * 32 + j * 16],
                c[i][j], ldc, wmma::mem_row_major);
}

// ---------------------------------------------------------------------------
// fp32 -> fp16 hi(/lo) conversion
// ---------------------------------------------------------------------------
__global__ void cvt_kernel(const float* __restrict__ in, __half* __restrict__ hi,
                           __half* __restrict__ lo, int n4)
{
    int i = blockIdx.x * blockDim.x + threadIdx.x;
    if (i >= n4) return;
    float4 v = ((const float4*)in)[i];
    __half h0 = __float2half_rn(v.x), h1 = __float2half_rn(v.y);
    __half h2 = __float2half_rn(v.z), h3 = __float2half_rn(v.w);
    ((__half2*)hi)[i * 2 + 0] = __halves2half2(h0, h1);
    ((__half2*)hi)[i * 2 + 1] = __halves2half2(h2, h3);
    if (lo) {
        __half l0 = __float2half_rn(v.x - __half2float(h0));
        __half l1 = __float2half_rn(v.y - __half2float(h1));
        __half l2 = __float2half_rn(v.z - __half2float(h2));
        __half l3 = __float2half_rn(v.w - __half2float(h3));
        ((__half2*)lo)[i * 2 + 0] = __halves2half2(l0, l1);
        ((__half2*)lo)[i * 2 + 1] = __halves2half2(l2, l3);
    }
}

// ---------------------------------------------------------------------------
// Router + combine (one warp/token): logits=||g_e||, top-2, 2-way softmax.
// zc[t,0:256]=z*w (fp16), [256:264]=w_dense, [264]=1.0 (bias hook), pad=0.
// ---------------------------------------------------------------------------
__global__ __launch_bounds__(256) void router_combine_kernel(
    const float* __restrict__ g, const float* __restrict__ z, __half* __restrict__ zc)
{
    const int tok  = (blockIdx.x * blockDim.x + threadIdx.x) >> 5;
    const int lane = threadIdx.x & 31;
    if (tok >= T_TOK) return;

    float4 gv = *(const float4*)&g[(size_t)tok * GATE_N + lane * 4];
    float s = gv.x * gv.x + gv.y * gv.y + gv.z * gv.z + gv.w * gv.w;
    s += __shfl_xor_sync(0xffffffffu, s, 1);
    s += __shfl_xor_sync(0xffffffffu, s, 2);
    float logit = sqrtf(s);

    float l[N_EXP];
#pragma unroll
    for (int e = 0; e < N_EXP; e++)
        l[e] = __shfl_sync(0xffffffffu, logit, e * 4);

    int i1 = 0; float m1 = l[0];
#pragma unroll
    for (int e = 1; e < N_EXP; e++) if (l[e] > m1) { m1 = l[e]; i1 = e; }
    int i2 = (i1 == 0) ? 1 : 0; float m2 = l[i2];
#pragma unroll
    for (int e = 0; e < N_EXP; e++)
        if (e != i1 && e != i2 && l[e] > m2) { m2 = l[e]; i2 = e; }

    float r  = expf(m2 - m1);
    float w1 = 1.0f / (1.0f + r);
    float w2 = r * w1;

    int e = lane >> 2;
    float w = (e == i1) ? w1 : ((e == i2) ? w2 : 0.0f);
    const float4* zr = (const float4*)&z[(size_t)tok * Z_N + lane * 8];
    float4 a = zr[0], b = zr[1];
    __half2* zo = (__half2*)&zc[(size_t)tok * K2P + lane * 8];
    zo[0] = __floats2half2_rn(a.x * w, a.y * w);
    zo[1] = __floats2half2_rn(a.z * w, a.w * w);
    zo[2] = __floats2half2_rn(b.x * w, b.y * w);
    zo[3] = __floats2half2_rn(b.z * w, b.w * w);

    for (int c = Z_N + lane; c < K2P; c += 32) {
        float v = 0.0f;
        if (c < Z_N + N_EXP) {
            int ee = c - Z_N;
            v = (ee == i1) ? w1 : ((ee == i2) ? w2 : 0.0f);
        } else if (c == Z_N + N_EXP) {
            v = 1.0f;                     // constant-1 column -> picks up bias b
        }
        zc[(size_t)tok * K2P + c] = __float2half_rn(v);
    }
}

// U2[OUT_F,K2P]: 0..255 u[e][o][k] at e*32+k, 256..263 expert_bias, 264 b, pad 0
__global__ void build_u2_kernel(const float* __restrict__ u, const float* __restrict__ eb,
                                const float* __restrict__ b, __half* __restrict__ u2)
{
    int idx = blockIdx.x * blockDim.x + threadIdx.x;
    if (idx >= OUT_F * K2P) return;
    int o = idx / K2P, c = idx % K2P;
    float v = 0.0f;
    if (c < Z_N) {
        int e = c >> 5, k = c & 31;
        v = u[((size_t)e * OUT_F + o) * 32 + k];
    } else if (c < Z_N + N_EXP) {
        v = eb[(size_t)(c - Z_N) * OUT_F + o];
    } else if (c == Z_N + N_EXP) {
        v = b[o];
    }
    u2[(size_t)o * K2P + c] = __float2half_rn(v);
}

// ---------------------------------------------------------------------------
extern "C" void kernel_launch(void* const* d_in, const int* in_sizes, int n_in,
                              void* d_out, int out_size)
{
    const float* x      = (const float*)d_in[0];
    const float* W      = (const float*)d_in[1];
    const float* b      = (const float*)d_in[2];
    const float* gate_w = (const float*)d_in[3];
    const float* u      = (const float*)d_in[4];
    const float* svh    = (const float*)d_in[5];
    const float* eb     = (const float*)d_in[6];
    float* out          = (float*)d_out;

    __half *xh, *xl, *Wh, *gwh, *gwl, *svhh, *zc, *u2;
    float *gp, *zp;
    cudaGetSymbolAddress((void**)&xh, g_xh);
    cudaGetSymbolAddress((void**)&xl, g_xl);
    cudaGetSymbolAddress((void**)&Wh, g_Wh);
    cudaGetSymbolAddress((void**)&gwh, g_gwh);
    cudaGetSymbolAddress((void**)&gwl, g_gwl);
    cudaGetSymbolAddress((void**)&svhh, g_svh);
    cudaGetSymbolAddress((void**)&gp, g_g);
    cudaGetSymbolAddress((void**)&zp, g_z);
    cudaGetSymbolAddress((void**)&zc, g_zc);
    cudaGetSymbolAddress((void**)&u2, g_u2);

    const size_t smem_256 = (size_t)3 * (128 + 256) * SKT * sizeof(__half);   // 92,160
    const size_t smem_128 = (size_t)3 * (128 + 128) * SKT * sizeof(__half);   // 61,440
    const size_t smem_split = (size_t)2 * (2 * 128 * SKT + 2 * 64 * SKT) * sizeof(__half);
    cudaFuncSetAttribute(gemm_f16_big<256>,
                         cudaFuncAttributeMaxDynamicSharedMemorySize, (int)smem_256);
    cudaFuncSetAttribute(gemm_f16_big<128>,
                         cudaFuncAttributeMaxDynamicSharedMemorySize, (int)smem_128);
    cudaFuncSetAttribute(gemm_split_kernel,
                         cudaFuncAttributeMaxDynamicSharedMemorySize, (int)smem_split);

    // 1. conversions + u2
    cvt_kernel<<<(T_TOK * IN_F / 4 + 255) / 256, 256>>>(x, xh, xl, T_TOK * IN_F / 4);
    cvt_kernel<<<(OUT_F * IN_F / 4 + 255) / 256, 256>>>(W, Wh, nullptr, OUT_F * IN_F / 4);
    cvt_kernel<<<(GATE_N * IN_F / 4 + 255) / 256, 256>>>(gate_w, gwh, gwl, GATE_N * IN_F / 4);
    cvt_kernel<<<(Z_N * IN_F / 4 + 255) / 256, 256>>>(svh, svhh, nullptr, Z_N * IN_F / 4);
    build_u2_kernel<<<(OUT_F * K2P + 255) / 256, 256>>>(u, eb, b, u2);

    // 2. gate logits (split fp16 ~ fp32 accuracy)
    gemm_split_kernel<<<dim3(GATE_N / 64, T_TOK / 128), 256, smem_split>>>(
        xh, xl, IN_F, gwh, gwl, IN_F, gp, GATE_N, IN_F);

    // 3. z = x @ svh^T  (128-wide tiles -> 128 CTAs)
    gemm_f16_big<128><<<dim3(Z_N / 128, T_TOK / 128), 256, smem_128>>>(
        xh, IN_F, xh, IN_F, svhh, IN_F, svhh, IN_F, zp, Z_N, IN_F, IN_F);

    // 4. router + weighted combine -> zc
    router_combine_kernel<<<T_TOK / 8, 256>>>(gp, zp, zc);

    // 5. out = [x | zc] @ [W | u2]^T   (pre + bias + moe + expert_bias, one pass)
    gemm_f16_big<256><<<dim3(OUT_F / 256, T_TOK / 128), 256, smem_256>>>(
        xh, IN_F, zc, K2P, Wh, IN_F, u2, K2P, out, OUT_F, IN_F, KTOT);
}

// round 13
// speedup vs baseline: 1.3229x; 1.3229x over previous
#include <cuda_runtime.h>
#include <cuda_fp16.h>
#include <mma.h>
#include <cstdint>

using namespace nvcuda;

// Problem constants (fixed by setup_inputs)
#define T_TOK   8192
#define IN_F    2048
#define OUT_F   2048
#define N_EXP   8
#define GATE_N  128
#define Z_N     256
#define K2P     320               // 256 z + 8 w_dense + 1 const-one + 55 pad
#define KTOT    (IN_F + K2P)      // 2368

// ---------------------------------------------------------------------------
// Static device scratch (no allocation allowed)
// ---------------------------------------------------------------------------
__device__ __half g_xh[(size_t)T_TOK * IN_F];
__device__ __half g_xl[(size_t)T_TOK * IN_F];
__device__ __half g_Wh[(size_t)OUT_F * IN_F];
__device__ __half g_gwh[GATE_N * IN_F];
__device__ __half g_gwl[GATE_N * IN_F];
__device__ __half g_svh[Z_N * IN_F];
__device__ float  g_g[(size_t)T_TOK * GATE_N];
__device__ float  g_z[(size_t)T_TOK * Z_N];
__device__ __half g_zc[(size_t)T_TOK * K2P];
__device__ __half g_u2[(size_t)OUT_F * K2P];

// ---------------------------------------------------------------------------
__device__ __forceinline__ uint32_t smem_u32(const void* p) {
    uint32_t a;
    asm("{ .reg .u64 t; cvta.to.shared.u64 t, %1; cvt.u32.u64 %0, t; }"
        : "=r"(a) : "l"(p));
    return a;
}
__device__ __forceinline__ void cp16(uint32_t saddr, const void* gaddr) {
    asm volatile("cp.async.cg.shared.global [%0], [%1], 16;" :: "r"(saddr), "l"(gaddr));
}
__device__ __forceinline__ void cp_commit() {
    asm volatile("cp.async.commit_group;" ::: "memory");
}
template<int N>
__device__ __forceinline__ void cp_wait() {
    asm volatile("cp.async.wait_group %0;" :: "n"(N) : "memory");
}

// BK=64: smem row stride = 72 halves (64 data + 8 pad) = 144 bytes.
// Rows rotate banks by 16B (144 mod 128) -> conflict-free LDSM / stores.
#define SKT 72
#define ROWB 144

// ---------------------------------------------------------------------------
// fp16 wmma GEMM, C[M,N] = A[M,K]@B[N,K]^T, fp32 store.
// Dual-segment K: cols [0,K0) from A0/B0, cols [K0,Ktot) from A1/B1.
// BM=128, BN=128, BK=64, 256 threads (8 warps as 4x2; warp tile 32x64).
// 3-stage cp.async pipeline, ONE __syncthreads per k-tile.
// ---------------------------------------------------------------------------
__global__ __launch_bounds__(256) void gemm_f16_kernel(
    const __half* __restrict__ A0, int lda0, const __half* __restrict__ A1, int lda1,
    const __half* __restrict__ B0, int ldb0, const __half* __restrict__ B1, int ldb1,
    float* __restrict__ C, int ldc, int K0, int Ktot)
{
    extern __shared__ __half sm[];
    constexpr int ATL  = 128 * SKT;            // halves
    constexpr int STG  = 2 * ATL;              // A + B per stage (halves)
    constexpr int ATLB = 128 * ROWB;           // bytes
    constexpr int STGB = 2 * ATLB;
    const uint32_t sbase = smem_u32(sm);

    const int tid = threadIdx.x;
    const int wid = tid >> 5;
    const int wrow = wid >> 1;                 // 0..3 -> 32-row band
    const int wcol = wid & 1;                  // 0..1 -> 64-col band
    const int m0 = blockIdx.y * 128;
    const int n0 = blockIdx.x * 128;

    wmma::fragment<wmma::accumulator, 16, 16, 16, float> c[2][4];
#pragma unroll
    for (int i = 0; i < 2; i++)
#pragma unroll
        for (int j = 0; j < 4; j++)
            wmma::fill_fragment(c[i][j], 0.0f);

    const int nt = Ktot / 64;

    auto load_tile = [&](int kt) {
        const int k0 = kt * 64;
        const __half* Asrc; int lda; int ka;
        const __half* Bsrc; int ldb;
        if (k0 < K0) { Asrc = A0; lda = lda0; Bsrc = B0; ldb = ldb0; ka = k0; }
        else         { Asrc = A1; lda = lda1; Bsrc = B1; ldb = ldb1; ka = k0 - K0; }
        const uint32_t st = sbase + (kt % 3) * STGB;
        // 256 rows x 8 chunks of 16B = 2048 chunks; 8 per thread
#pragma unroll
        for (int base = 0; base < 2048; base += 256) {
            int idx = base + tid;
            int r = idx >> 3, q = idx & 7;
            if (r < 128)
                cp16(st + r * ROWB + q * 16, Asrc + (size_t)(m0 + r) * lda + ka + q * 8);
            else
                cp16(st + ATLB + (r - 128) * ROWB + q * 16,
                     Bsrc + (size_t)(n0 + r - 128) * ldb + ka + q * 8);
        }
        cp_commit();
    };

    auto compute = [&](int kt) {
        __half* Asm = sm + (kt % 3) * STG;
        __half* Bsm = Asm + ATL;
#pragma unroll
        for (int kk = 0; kk < 64; kk += 16) {
            wmma::fragment<wmma::matrix_a, 16, 16, 16, __half, wmma::row_major> a[2];
            wmma::fragment<wmma::matrix_b, 16, 16, 16, __half, wmma::col_major> bf[4];
#pragma unroll
            for (int i = 0; i < 2; i++)
                wmma::load_matrix_sync(a[i], &Asm[(wrow * 32 + i * 16) * SKT + kk], SKT);
#pragma unroll
            for (int j = 0; j < 4; j++)
                wmma::load_matrix_sync(bf[j], &Bsm[(wcol * 64 + j * 16) * SKT + kk], SKT);
#pragma unroll
            for (int i = 0; i < 2; i++)
#pragma unroll
                for (int j = 0; j < 4; j++)
                    wmma::mma_sync(c[i][j], a[i], bf[j], c[i][j]);
        }
    };

    load_tile(0);
    load_tile(1);
    for (int kt = 0; kt < nt; kt++) {
        if (kt + 1 < nt) cp_wait<1>(); else cp_wait<0>();
        __syncthreads();                      // stage kt visible; compute(kt-1) done
        if (kt + 2 < nt) load_tile(kt + 2);   // overwrites stage (kt-1)%3 — safe now
        compute(kt);
    }

#pragma unroll
    for (int i = 0; i < 2; i++)
#pragma unroll
        for (int j = 0; j < 4; j++)
            wmma::store_matrix_sync(
                &C[(size_t)(m0 + wrow * 32 + i * 16) * ldc + n0 + wcol * 64 + j * 16],
                c[i][j], ldc, wmma::mem_row_major);
}

// ---------------------------------------------------------------------------
// Split (hi/lo) fp16 GEMM for the gate: ~fp32 accuracy (3 MMAs per frag).
// BM=128, BN=64, BK=64, 256 threads (8 warps as 4x2, warp tile 32x32).
// 3-stage pipeline, one sync per k-tile.
// ---------------------------------------------------------------------------
__global__ __launch_bounds__(256) void gemm_split_kernel(
    const __half* __restrict__ Ah, const __half* __restrict__ Al, int lda,
    const __half* __restrict__ Bh, const __half* __restrict__ Bl, int ldb,
    float* __restrict__ C, int ldc, int Ktot)
{
    extern __shared__ __half sm[];
    constexpr int ATL  = 128 * SKT;            // halves
    constexpr int BTL  = 64 * SKT;
    constexpr int STG  = 2 * ATL + 2 * BTL;    // Ah, Al, Bh, Bl (halves)
    constexpr int ATLB = 128 * ROWB;
    constexpr int BTLB = 64 * ROWB;
    constexpr int STGB = 2 * ATLB + 2 * BTLB;
    const uint32_t sbase = smem_u32(sm);

    const int tid = threadIdx.x;
    const int wid = tid >> 5;
    const int wrow = wid >> 1;
    const int wcol = wid & 1;
    const int m0 = blockIdx.y * 128;
    const int n0 = blockIdx.x * 64;

    wmma::fragment<wmma::accumulator, 16, 16, 16, float> c[2][2];
#pragma unroll
    for (int i = 0; i < 2; i++)
#pragma unroll
        for (int j = 0; j < 2; j++)
            wmma::fill_fragment(c[i][j], 0.0f);

    const int nt = Ktot / 64;

    auto load_tile = [&](int kt) {
        const int k0 = kt * 64;
        const uint32_t st = sbase + (kt % 3) * STGB;
        // rows: Ah 0..127, Al 128..255, Bh 256..319, Bl 320..383; 8 chunks each
#pragma unroll
        for (int base = 0; base < 384 * 8; base += 256) {
            int idx = base + tid;
            int r = idx >> 3, q = idx & 7;
            if (r < 128)
                cp16(st + r * ROWB + q * 16, Ah + (size_t)(m0 + r) * lda + k0 + q * 8);
            else if (r < 256)
                cp16(st + ATLB + (r - 128) * ROWB + q * 16,
                     Al + (size_t)(m0 + r - 128) * lda + k0 + q * 8);
            else if (r < 320)
                cp16(st + 2 * ATLB + (r - 256) * ROWB + q * 16,
                     Bh + (size_t)(n0 + r - 256) * ldb + k0 + q * 8);
            else
                cp16(st + 2 * ATLB + BTLB + (r - 320) * ROWB + q * 16,
                     Bl + (size_t)(n0 + r - 320) * ldb + k0 + q * 8);
        }
        cp_commit();
    };

    auto compute = [&](int kt) {
        __half* AhS = sm + (kt % 3) * STG;
        __half* AlS = AhS + ATL;
        __half* BhS = AlS + ATL;
        __half* BlS = BhS + BTL;
#pragma unroll
        for (int kk = 0; kk < 64; kk += 16) {
            wmma::fragment<wmma::matrix_a, 16, 16, 16, __half, wmma::row_major> ah[2], al[2];
            wmma::fragment<wmma::matrix_b, 16, 16, 16, __half, wmma::col_major> bh[2], bl[2];
#pragma unroll
            for (int i = 0; i < 2; i++) {
                wmma::load_matrix_sync(ah[i], &AhS[(wrow * 32 + i * 16) * SKT + kk], SKT);
                wmma::load_matrix_sync(al[i], &AlS[(wrow * 32 + i * 16) * SKT + kk], SKT);
            }
#pragma unroll
            for (int j = 0; j < 2; j++) {
                wmma::load_matrix_sync(bh[j], &BhS[(wcol * 32 + j * 16) * SKT + kk], SKT);
                wmma::load_matrix_sync(bl[j], &BlS[(wcol * 32 + j * 16) * SKT + kk], SKT);
            }
#pragma unroll
            for (int i = 0; i < 2; i++)
#pragma unroll
                for (int j = 0; j < 2; j++) {
                    wmma::mma_sync(c[i][j], ah[i], bl[j], c[i][j]);
                    wmma::mma_sync(c[i][j], al[i], bh[j], c[i][j]);
                    wmma::mma_sync(c[i][j], ah[i], bh[j], c[i][j]);
                }
        }
    };

    load_tile(0);
    load_tile(1);
    for (int kt = 0; kt < nt; kt++) {
        if (kt + 1 < nt) cp_wait<1>(); else cp_wait<0>();
        __syncthreads();
        if (kt + 2 < nt) load_tile(kt + 2);
        compute(kt);
    }

#pragma unroll
    for (int i = 0; i < 2; i++)
#pragma unroll
        for (int j = 0; j < 2; j++)
            wmma::store_matrix_sync(
                &C[(size_t)(m0 + wrow * 32 + i * 16) * ldc + n0 + wcol * 32 + j * 16],
                c[i][j], ldc, wmma::mem_row_major);
}

// ---------------------------------------------------------------------------
// fp32 -> fp16 hi(/lo) conversion
// ---------------------------------------------------------------------------
__global__ void cvt_kernel(const float* __restrict__ in, __half* __restrict__ hi,
                           __half* __restrict__ lo, int n4)
{
    int i = blockIdx.x * blockDim.x + threadIdx.x;
    if (i >= n4) return;
    float4 v = ((const float4*)in)[i];
    __half h0 = __float2half_rn(v.x), h1 = __float2half_rn(v.y);
    __half h2 = __float2half_rn(v.z), h3 = __float2half_rn(v.w);
    ((__half2*)hi)[i * 2 + 0] = __halves2half2(h0, h1);
    ((__half2*)hi)[i * 2 + 1] = __halves2half2(h2, h3);
    if (lo) {
        __half l0 = __float2half_rn(v.x - __half2float(h0));
        __half l1 = __float2half_rn(v.y - __half2float(h1));
        __half l2 = __float2half_rn(v.z - __half2float(h2));
        __half l3 = __float2half_rn(v.w - __half2float(h3));
        ((__half2*)lo)[i * 2 + 0] = __halves2half2(l0, l1);
        ((__half2*)lo)[i * 2 + 1] = __halves2half2(l2, l3);
    }
}

// ---------------------------------------------------------------------------
// Router + combine (one warp/token): logits=||g_e||, top-2, 2-way softmax.
// zc[t,0:256]=z*w (fp16), [256:264]=w_dense, [264]=1.0 (bias hook), pad=0.
// ---------------------------------------------------------------------------
__global__ __launch_bounds__(256) void router_combine_kernel(
    const float* __restrict__ g, const float* __restrict__ z, __half* __restrict__ zc)
{
    const int tok  = (blockIdx.x * blockDim.x + threadIdx.x) >> 5;
    const int lane = threadIdx.x & 31;
    if (tok >= T_TOK) return;

    float4 gv = *(const float4*)&g[(size_t)tok * GATE_N + lane * 4];
    float s = gv.x * gv.x + gv.y * gv.y + gv.z * gv.z + gv.w * gv.w;
    s += __shfl_xor_sync(0xffffffffu, s, 1);
    s += __shfl_xor_sync(0xffffffffu, s, 2);
    float logit = sqrtf(s);

    float l[N_EXP];
#pragma unroll
    for (int e = 0; e < N_EXP; e++)
        l[e] = __shfl_sync(0xffffffffu, logit, e * 4);

    int i1 = 0; float m1 = l[0];
#pragma unroll
    for (int e = 1; e < N_EXP; e++) if (l[e] > m1) { m1 = l[e]; i1 = e; }
    int i2 = (i1 == 0) ? 1 : 0; float m2 = l[i2];
#pragma unroll
    for (int e = 0; e < N_EXP; e++)
        if (e != i1 && e != i2 && l[e] > m2) { m2 = l[e]; i2 = e; }

    float r  = expf(m2 - m1);
    float w1 = 1.0f / (1.0f + r);
    float w2 = r * w1;

    int e = lane >> 2;
    float w = (e == i1) ? w1 : ((e == i2) ? w2 : 0.0f);
    const float4* zr = (const float4*)&z[(size_t)tok * Z_N + lane * 8];
    float4 a = zr[0], b = zr[1];
    __half2* zo = (__half2*)&zc[(size_t)tok * K2P + lane * 8];
    zo[0] = __floats2half2_rn(a.x * w, a.y * w);
    zo[1] = __floats2half2_rn(a.z * w, a.w * w);
    zo[2] = __floats2half2_rn(b.x * w, b.y * w);
    zo[3] = __floats2half2_rn(b.z * w, b.w * w);

    for (int c = Z_N + lane; c < K2P; c += 32) {
        float v = 0.0f;
        if (c < Z_N + N_EXP) {
            int ee = c - Z_N;
            v = (ee == i1) ? w1 : ((ee == i2) ? w2 : 0.0f);
        } else if (c == Z_N + N_EXP) {
            v = 1.0f;                     // constant-1 column -> picks up bias b
        }
        zc[(size_t)tok * K2P + c] = __float2half_rn(v);
    }
}

// U2[OUT_F,K2P]: 0..255 u[e][o][k] at e*32+k, 256..263 expert_bias, 264 b, pad 0
__global__ void build_u2_kernel(const float* __restrict__ u, const float* __restrict__ eb,
                                const float* __restrict__ b, __half* __restrict__ u2)
{
    int idx = blockIdx.x * blockDim.x + threadIdx.x;
    if (idx >= OUT_F * K2P) return;
    int o = idx / K2P, c = idx % K2P;
    float v = 0.0f;
    if (c < Z_N) {
        int e = c >> 5, k = c & 31;
        v = u[((size_t)e * OUT_F + o) * 32 + k];
    } else if (c < Z_N + N_EXP) {
        v = eb[(size_t)(c - Z_N) * OUT_F + o];
    } else if (c == Z_N + N_EXP) {
        v = b[o];
    }
    u2[(size_t)o * K2P + c] = __float2half_rn(v);
}

// ---------------------------------------------------------------------------
extern "C" void kernel_launch(void* const* d_in, const int* in_sizes, int n_in,
                              void* d_out, int out_size)
{
    const float* x      = (const float*)d_in[0];
    const float* W      = (const float*)d_in[1];
    const float* b      = (const float*)d_in[2];
    const float* gate_w = (const float*)d_in[3];
    const float* u      = (const float*)d_in[4];
    const float* svh    = (const float*)d_in[5];
    const float* eb     = (const float*)d_in[6];
    float* out          = (float*)d_out;

    __half *xh, *xl, *Wh, *gwh, *gwl, *svhh, *zc, *u2;
    float *gp, *zp;
    cudaGetSymbolAddress((void**)&xh, g_xh);
    cudaGetSymbolAddress((void**)&xl, g_xl);
    cudaGetSymbolAddress((void**)&Wh, g_Wh);
    cudaGetSymbolAddress((void**)&gwh, g_gwh);
    cudaGetSymbolAddress((void**)&gwl, g_gwl);
    cudaGetSymbolAddress((void**)&svhh, g_svh);
    cudaGetSymbolAddress((void**)&gp, g_g);
    cudaGetSymbolAddress((void**)&zp, g_z);
    cudaGetSymbolAddress((void**)&zc, g_zc);
    cudaGetSymbolAddress((void**)&u2, g_u2);

    const size_t smem_main  = (size_t)3 * 2 * 128 * ROWB;                  // 110,592
    const size_t smem_split = (size_t)3 * (2 * 128 + 2 * 64) * ROWB;       // 165,888
    cudaFuncSetAttribute(gemm_f16_kernel,
                         cudaFuncAttributeMaxDynamicSharedMemorySize, (int)smem_main);
    cudaFuncSetAttribute(gemm_split_kernel,
                         cudaFuncAttributeMaxDynamicSharedMemorySize, (int)smem_split);

    // 1. conversions + u2
    cvt_kernel<<<(T_TOK * IN_F / 4 + 255) / 256, 256>>>(x, xh, xl, T_TOK * IN_F / 4);
    cvt_kernel<<<(OUT_F * IN_F / 4 + 255) / 256, 256>>>(W, Wh, nullptr, OUT_F * IN_F / 4);
    cvt_kernel<<<(GATE_N * IN_F / 4 + 255) / 256, 256>>>(gate_w, gwh, gwl, GATE_N * IN_F / 4);
    cvt_kernel<<<(Z_N * IN_F / 4 + 255) / 256, 256>>>(svh, svhh, nullptr, Z_N * IN_F / 4);
    build_u2_kernel<<<(OUT_F * K2P + 255) / 256, 256>>>(u, eb, b, u2);

    // 2. gate logits (split fp16 ~ fp32 accuracy)
    gemm_split_kernel<<<dim3(GATE_N / 64, T_TOK / 128), 256, smem_split>>>(
        xh, xl, IN_F, gwh, gwl, IN_F, gp, GATE_N, IN_F);

    // 3. z = x @ svh^T
    gemm_f16_kernel<<<dim3(Z_N / 128, T_TOK / 128), 256, smem_main>>>(
        xh, IN_F, xh, IN_F, svhh, IN_F, svhh, IN_F, zp, Z_N, IN_F, IN_F);

    // 4. router + weighted combine -> zc
    router_combine_kernel<<<T_TOK / 8, 256>>>(gp, zp, zc);

    // 5. out = [x | zc] @ [W | u2]^T   (pre + bias + moe + expert_bias, one pass)
    gemm_f16_kernel<<<dim3(OUT_F / 128, T_TOK / 128), 256, smem_main>>>(
        xh, IN_F, zc, K2P, Wh, IN_F, u2, K2P, out, OUT_F, IN_F, KTOT);
}